// round 2
// baseline (speedup 1.0000x reference)
#include <cuda_runtime.h>

#define BB 4096
#define TT 400
#define CC 42
#define HH 16

// Scratch: U[bblk(256)][t(400)][ploc(8)][i(16)] as f32x2 pairs (lo=even batch, hi=odd batch)
__device__ __align__(16) unsigned long long g_U[256ull * TT * 8 * 16];

// ---------- f32x2 helpers ----------
__device__ __forceinline__ unsigned long long pk2(float lo, float hi) {
    unsigned long long r;
    asm("mov.b64 %0, {%1, %2};" : "=l"(r) : "f"(lo), "f"(hi));
    return r;
}
__device__ __forceinline__ void up2(unsigned long long v, float& a, float& b) {
    asm("mov.b64 {%0, %1}, %2;" : "=f"(a), "=f"(b) : "l"(v));
}
__device__ __forceinline__ unsigned long long fma2(unsigned long long a, unsigned long long b,
                                                   unsigned long long c) {
    unsigned long long d;
    asm("fma.rn.f32x2 %0, %1, %2, %3;" : "=l"(d) : "l"(a), "l"(b), "l"(c));
    return d;
}
__device__ __forceinline__ unsigned long long add2(unsigned long long a, unsigned long long b) {
    unsigned long long d;
    asm("add.rn.f32x2 %0, %1, %2;" : "=l"(d) : "l"(a), "l"(b));
    return d;
}
// tanh(x) = 1 - 2/(1+e^{2x}); ex2/rcp approx => ~1e-7 rel err, saturates correctly
__device__ __forceinline__ float tanh_f(float x) {
    float e, r;
    asm("ex2.approx.f32 %0, %1;" : "=f"(e) : "f"(x * 2.8853900817779268f));
    asm("rcp.approx.f32 %0, %1;" : "=f"(r) : "f"(e + 1.0f));
    return fmaf(-2.0f, r, 1.0f);
}

// ---------- Kernel A: U[b,t,:] = bias0 + W_ih0 @ x[b,:,t]  (smem-tiled, coalesced) ----------
// Block: (bblk = 16 batches = 8 pairs) x (16 timesteps). grid = (25, 256).
// Phase1: coalesced float4 loads of x into smem, packed as f32x2 batch pairs.
// Phase2: thread = (ploc, i): 16 accumulators over t; coalesced 256B/warp stores.
__global__ void __launch_bounds__(128) kA(const float* __restrict__ x,
                                          const float* __restrict__ Wih0,
                                          const float* __restrict__ bih0,
                                          const float* __restrict__ bhh0) {
    __shared__ __align__(16) unsigned long long s_x[CC][8][16];  // [c][ploc][t] f32x2
    __shared__ float sw[CC * HH];                                // copy of Wih0 [i][c]

    int tid = threadIdx.x;
    int tchunk = blockIdx.x;   // 0..24
    int bblk = blockIdx.y;     // 0..255
    int t0 = tchunk * 16;

    // stage weights
    for (int k = tid; k < CC * HH; k += 128) sw[k] = Wih0[k];

    // phase 1: load x tile (16 b x 42 c x 16 t), fully coalesced float4 rows
    const size_t xbase = (size_t)bblk * 16 * (CC * TT) + t0;
    for (int k = tid; k < 16 * CC * 4; k += 128) {  // 2688 float4 loads
        int r = k >> 2, q = k & 3;
        int bl = r / CC;
        int c = r - bl * CC;
        float4 v = *(const float4*)(x + xbase + (size_t)bl * (CC * TT) + c * TT + q * 4);
        float* base = ((float*)&s_x[c][bl >> 1][0]) + (bl & 1);
        base[(q * 4 + 0) * 2] = v.x;
        base[(q * 4 + 1) * 2] = v.y;
        base[(q * 4 + 2) * 2] = v.z;
        base[(q * 4 + 3) * 2] = v.w;
    }
    __syncthreads();

    // phase 2
    int i = tid & 15;
    int ploc = tid >> 4;
    float bs = bih0[i] + bhh0[i];
    unsigned long long b2 = pk2(bs, bs);
    unsigned long long acc[16];
#pragma unroll
    for (int t = 0; t < 16; t++) acc[t] = b2;

#pragma unroll 6
    for (int c = 0; c < CC; c++) {
        float wv = sw[i * CC + c];
        unsigned long long w2 = pk2(wv, wv);
        const ulonglong2* xp = (const ulonglong2*)&s_x[c][ploc][0];
#pragma unroll
        for (int tp = 0; tp < 8; tp++) {
            ulonglong2 xv = xp[tp];
            acc[2 * tp]     = fma2(w2, xv.x, acc[2 * tp]);
            acc[2 * tp + 1] = fma2(w2, xv.y, acc[2 * tp + 1]);
        }
    }

    // coalesced stores: per t, warp writes 256B contiguous
    unsigned long long* dst = g_U + ((size_t)bblk * TT + t0) * 128 + ploc * 16 + i;
#pragma unroll
    for (int t = 0; t < 16; t++) dst[(size_t)t * 128] = acc[t];
}

// ---------- Kernel B: fused 2-layer recurrence + final FC (split-dot, 2048 warps) ----------
// warp = 1 batch pair. lane = (i = hidden unit 0..15, h = half 0..1).
// Lane computes 8-term partials (f32x2, both batches); shfl.bfly combines across halves;
// tanh distributed: lane handles the scalar for batch h of output i.
__global__ void __launch_bounds__(128) kB(const float* __restrict__ h0in,
                                          const float* __restrict__ Whh0,
                                          const float* __restrict__ Wih1,
                                          const float* __restrict__ Whh1,
                                          const float* __restrict__ bih1,
                                          const float* __restrict__ bhh1,
                                          const float* __restrict__ Wfc,
                                          const float* __restrict__ bfc,
                                          float* __restrict__ out) {
    __shared__ __align__(16) float sh0[4][32];  // [warp][i*2+h] : float2 per i = (b0, b1)
    __shared__ __align__(16) float sh1[4][32];

    int tid = threadIdx.x;
    int w = tid >> 5;
    int lane = tid & 31;
    int i = lane & 15;
    int h = lane >> 4;
    int p = blockIdx.x * 4 + w;  // pair 0..2047
    int bblk = p >> 3, ploc = p & 7;
    int b0 = 2 * p, b1 = b0 + 1;
    int j0 = 8 * h;

    // weight partial rows (duplicated f32x2)
    unsigned long long wh0[8], wi1[8], wh1[8];
#pragma unroll
    for (int jj = 0; jj < 8; jj++) {
        int j = j0 + jj;
        float v0 = Whh0[i * 16 + j];
        float v1 = Wih1[i * 16 + j];
        float v2 = Whh1[i * 16 + j];
        wh0[jj] = pk2(v0, v0);
        wi1[jj] = pk2(v1, v1);
        wh1[jj] = pk2(v2, v2);
    }
    float bias1 = bih1[i] + bhh1[i];

    // initial hidden state (h0 layout (2, B, H))
    unsigned long long h0a[8], h1a[8];
#pragma unroll
    for (int jj = 0; jj < 8; jj++) {
        int j = j0 + jj;
        h0a[jj] = pk2(h0in[b0 * 16 + j], h0in[b1 * 16 + j]);
        h1a[jj] = pk2(h0in[BB * HH + b0 * 16 + j], h0in[BB * HH + b1 * 16 + j]);
    }

    // U stream: lane reads scalar float (batch h of output i); 128B/warp contiguous
    const float* uptr = ((const float*)g_U) + (size_t)bblk * TT * 256 + ploc * 32 + i * 2 + h;
    const float* ulast = uptr + (size_t)(TT - 1) * 256;
    float ub[4];
#pragma unroll
    for (int k = 0; k < 4; k++) ub[k] = uptr[k * 256];
    const float* upf = uptr + 4 * 256;

    float* my0 = &sh0[w][i * 2 + h];
    float* my1 = &sh1[w][i * 2 + h];
    const ulonglong2* r0 = (const ulonglong2*)((const unsigned long long*)&sh0[w][0] + j0);
    const ulonglong2* r1 = (const ulonglong2*)((const unsigned long long*)&sh1[w][0] + j0);

    for (int tb = 0; tb < TT; tb += 4) {
#pragma unroll
        for (int jj = 0; jj < 4; jj++) {
            float uf = ub[jj];
            const float* pf = upf;
            if (pf > ulast) pf = ulast;
            ub[jj] = *pf;
            upf += 256;

            // layer0 partial (two 4-deep chains)
            unsigned long long a0 = fma2(wh0[0], h0a[0], 0ull);
            unsigned long long a1 = fma2(wh0[1], h0a[1], 0ull);
            a0 = fma2(wh0[2], h0a[2], a0);
            a1 = fma2(wh0[3], h0a[3], a1);
            a0 = fma2(wh0[4], h0a[4], a0);
            a1 = fma2(wh0[5], h0a[5], a1);
            a0 = fma2(wh0[6], h0a[6], a0);
            a1 = fma2(wh0[7], h0a[7], a1);

            // layer1 recurrent partial (independent; overlaps l0 tanh/exchange)
            unsigned long long c0 = fma2(wh1[0], h1a[0], 0ull);
            unsigned long long c1 = fma2(wh1[1], h1a[1], 0ull);
            c0 = fma2(wh1[2], h1a[2], c0);
            c1 = fma2(wh1[3], h1a[3], c1);
            c0 = fma2(wh1[4], h1a[4], c0);
            c1 = fma2(wh1[5], h1a[5], c1);
            c0 = fma2(wh1[6], h1a[6], c0);
            c1 = fma2(wh1[7], h1a[7], c1);

            // combine halves for batch h, tanh, exchange
            unsigned long long pu = add2(a0, a1);
            float plo, phi;
            up2(pu, plo, phi);
            float mine = h ? phi : plo;
            float send = h ? plo : phi;
            float got = __shfl_xor_sync(0xffffffffu, send, 16);
            float hn = tanh_f(mine + got + uf);
            *my0 = hn;
            __syncwarp();
            {
                ulonglong2 v0 = r0[0], v1 = r0[1], v2 = r0[2], v3 = r0[3];
                h0a[0] = v0.x; h0a[1] = v0.y; h0a[2] = v1.x; h0a[3] = v1.y;
                h0a[4] = v2.x; h0a[5] = v2.y; h0a[6] = v3.x; h0a[7] = v3.y;
            }

            // layer1 input partial
            c0 = fma2(wi1[0], h0a[0], c0);
            c1 = fma2(wi1[1], h0a[1], c1);
            c0 = fma2(wi1[2], h0a[2], c0);
            c1 = fma2(wi1[3], h0a[3], c1);
            c0 = fma2(wi1[4], h0a[4], c0);
            c1 = fma2(wi1[5], h0a[5], c1);
            c0 = fma2(wi1[6], h0a[6], c0);
            c1 = fma2(wi1[7], h0a[7], c1);

            unsigned long long pc = add2(c0, c1);
            float qlo, qhi;
            up2(pc, qlo, qhi);
            float mine2 = h ? qhi : qlo;
            float send2 = h ? qlo : qhi;
            float got2 = __shfl_xor_sync(0xffffffffu, send2, 16);
            float hn1 = tanh_f(mine2 + got2 + bias1);
            *my1 = hn1;
            __syncwarp();
            {
                ulonglong2 v0 = r1[0], v1 = r1[1], v2 = r1[2], v3 = r1[3];
                h1a[0] = v0.x; h1a[1] = v0.y; h1a[2] = v1.x; h1a[3] = v1.y;
                h1a[4] = v2.x; h1a[5] = v2.y; h1a[6] = v3.x; h1a[7] = v3.y;
            }
        }
    }

    // final FC: out[b][c] = bfc[c] + sum_j Wfc[c][j] * h1[b][j]  (NC = 2)
    unsigned long long f0 = 0ull, f1 = 0ull;
#pragma unroll
    for (int jj = 0; jj < 8; jj++) {
        int j = j0 + jj;
        float w0 = Wfc[j], w1 = Wfc[16 + j];
        f0 = fma2(pk2(w0, w0), h1a[jj], f0);
        f1 = fma2(pk2(w1, w1), h1a[jj], f1);
    }
    float f0l, f0h, f1l, f1h;
    up2(f0, f0l, f0h);
    up2(f1, f1l, f1h);
    f0l += __shfl_xor_sync(0xffffffffu, f0l, 16);
    f0h += __shfl_xor_sync(0xffffffffu, f0h, 16);
    f1l += __shfl_xor_sync(0xffffffffu, f1l, 16);
    f1h += __shfl_xor_sync(0xffffffffu, f1h, 16);
    if (lane == 0) {
        float c0b = bfc[0], c1b = bfc[1];
        out[4 * p + 0] = f0l + c0b;
        out[4 * p + 1] = f1l + c1b;
        out[4 * p + 2] = f0h + c0b;
        out[4 * p + 3] = f1h + c1b;
    }
}

extern "C" void kernel_launch(void* const* d_in, const int* in_sizes, int n_in,
                              void* d_out, int out_size) {
    const float* x    = (const float*)d_in[0];
    const float* h0   = (const float*)d_in[1];
    const float* Wih0 = (const float*)d_in[2];
    const float* Whh0 = (const float*)d_in[3];
    const float* bih0 = (const float*)d_in[4];
    const float* bhh0 = (const float*)d_in[5];
    const float* Wih1 = (const float*)d_in[6];
    const float* Whh1 = (const float*)d_in[7];
    const float* bih1 = (const float*)d_in[8];
    const float* bhh1 = (const float*)d_in[9];
    const float* Wfc  = (const float*)d_in[10];
    const float* bfc  = (const float*)d_in[11];
    float* out = (float*)d_out;

    dim3 gA(25, 256);
    kA<<<gA, 128>>>(x, Wih0, bih0, bhh0);
    kB<<<512, 128>>>(h0, Whh0, Wih1, Whh1, bih1, bhh1, Wfc, bfc, out);
}

// round 3
// speedup vs baseline: 1.0300x; 1.0300x over previous
#include <cuda_runtime.h>

#define BB 4096
#define TT 400
#define CC 42
#define HH 16

// g_U[pair(2048)][t(400)][i(16)] as f32x2 (lo = even batch, hi = odd batch), pre-scaled
// by 2*log2(e). Plus a 16-u64 zero tail (never written; __device__ zero-init) that
// role-1 lanes in kB point their (dead) u-stream at.
#define ZTAIL (2048ull * TT * 16)
__device__ __align__(16) unsigned long long g_U[2048ull * TT * 16 + 16];

#define SCALE 2.885390081777927f  // 2 * log2(e)

// ---------- f32x2 helpers ----------
__device__ __forceinline__ unsigned long long pk2(float lo, float hi) {
    unsigned long long r;
    asm("mov.b64 %0, {%1, %2};" : "=l"(r) : "f"(lo), "f"(hi));
    return r;
}
__device__ __forceinline__ void up2(unsigned long long v, float& a, float& b) {
    asm("mov.b64 {%0, %1}, %2;" : "=f"(a), "=f"(b) : "l"(v));
}
__device__ __forceinline__ unsigned long long fma2(unsigned long long a, unsigned long long b,
                                                   unsigned long long c) {
    unsigned long long d;
    asm("fma.rn.f32x2 %0, %1, %2, %3;" : "=l"(d) : "l"(a), "l"(b), "l"(c));
    return d;
}
__device__ __forceinline__ unsigned long long add2(unsigned long long a, unsigned long long b) {
    unsigned long long d;
    asm("add.rn.f32x2 %0, %1, %2;" : "=l"(d) : "l"(a), "l"(b));
    return d;
}
// tanh with pre-scaled argument: z = 2*log2(e)*x  ->  tanh(x) = 1 - 2/(1+2^z)
__device__ __forceinline__ float tanh_pre(float z) {
    float e, r;
    asm("ex2.approx.f32 %0, %1;" : "=f"(e) : "f"(z));
    asm("rcp.approx.f32 %0, %1;" : "=f"(r) : "f"(e + 1.0f));
    return fmaf(-2.0f, r, 1.0f);
}
__device__ __forceinline__ unsigned long long tanh2_pre(unsigned long long z) {
    float a, b;
    up2(z, a, b);
    return pk2(tanh_pre(a), tanh_pre(b));
}

// ---------- Kernel A: U[p][t][:] = SCALE*(bias0 + W_ih0 @ x_t) ----------
// grid (25, 256), block 128. Warp = 2 pairs x 16 t (round-1 proven load pattern).
// Output staged in smem, then written to g_U fully coalesced (512B/warp/instr).
__global__ void __launch_bounds__(128) kA(const float* __restrict__ x,
                                          const float* __restrict__ Wih0,
                                          const float* __restrict__ bih0,
                                          const float* __restrict__ bhh0) {
    __shared__ __align__(16) unsigned long long swd[CC][HH];      // duplicated scaled weights
    __shared__ unsigned long long sb[HH];
    __shared__ __align__(16) unsigned long long sstage[128][18];  // [ploc*16+tl][i], padded

    int tid = threadIdx.x;
    for (int k = tid; k < CC * HH; k += 128) {
        int c = k >> 4, i = k & 15;
        float wv = SCALE * Wih0[i * CC + c];
        swd[c][i] = pk2(wv, wv);
    }
    if (tid < HH) {
        float b = SCALE * (bih0[tid] + bhh0[tid]);
        sb[tid] = pk2(b, b);
    }
    __syncthreads();

    int tc = blockIdx.x;   // 0..24
    int bblk = blockIdx.y; // 0..255
    int w = tid >> 5, lane = tid & 31;
    int s = lane >> 4, tl = lane & 15;
    int ploc = w * 2 + s;
    int p = bblk * 8 + ploc;
    int t = tc * 16 + tl;

    const float* xb0 = x + (size_t)(2 * p) * (CC * TT) + t;
    const float* xb1 = xb0 + (CC * TT);

    unsigned long long u[16];
#pragma unroll
    for (int i = 0; i < 16; i++) u[i] = sb[i];

#pragma unroll 7
    for (int c = 0; c < CC; c++) {
        float xa = xb0[c * TT];
        float xb = xb1[c * TT];
        unsigned long long xp = pk2(xa, xb);
        const ulonglong2* wp = (const ulonglong2*)&swd[c][0];
#pragma unroll
        for (int k = 0; k < 8; k++) {
            ulonglong2 w2 = wp[k];
            u[2 * k]     = fma2(w2.x, xp, u[2 * k]);
            u[2 * k + 1] = fma2(w2.y, xp, u[2 * k + 1]);
        }
    }

    // stage into smem
    {
        int row = ploc * 16 + tl;
        ulonglong2* st = (ulonglong2*)&sstage[row][0];
#pragma unroll
        for (int k = 0; k < 8; k++) st[k] = make_ulonglong2(u[2 * k], u[2 * k + 1]);
    }
    __syncthreads();

    // coalesced copy to g_U: warp w handles ploc = 2w, 2w+1; each chunk = 16 rows x 128B
#pragma unroll
    for (int cc = 0; cc < 2; cc++) {
        int pl2 = w * 2 + cc;
        unsigned long long* gdst = g_U + ((size_t)(bblk * 8 + pl2) * TT + tc * 16) * 16;
#pragma unroll
        for (int j = 0; j < 4; j++) {
            int g = j * 64 + lane * 2;  // u64 index within 256-u64 chunk
            int r2 = g >> 4, col = g & 15;
            ulonglong2 v = *(const ulonglong2*)&sstage[pl2 * 16 + r2][col];
            *(ulonglong2*)&gdst[g] = v;
        }
    }
}

// ---------- Kernel B: lane-level layer split, 2048 warps ----------
// warp = 1 pair. lane = i + 16*role. role0: layer0 (h0) + projection v = Wih1@h0 (+bias).
// role1: layer1 (h1), lagged one iteration, consuming v from smem. Uniform code path.
__global__ void __launch_bounds__(128, 4) kB(const float* __restrict__ h0in,
                                             const float* __restrict__ Whh0,
                                             const float* __restrict__ Wih1,
                                             const float* __restrict__ Whh1,
                                             const float* __restrict__ bih1,
                                             const float* __restrict__ bhh1,
                                             const float* __restrict__ Wfc,
                                             const float* __restrict__ bfc,
                                             float* __restrict__ out) {
    __shared__ __align__(16) unsigned long long sh[4][32];  // h exchange: [w][role*16+i]
    __shared__ __align__(16) unsigned long long sv[4][48];  // [0:16) v, [16:32) junk, [32:48) zeros

    int tid = threadIdx.x;
    int w = tid >> 5;
    int lane = tid & 31;
    int i = lane & 15;
    int role = lane >> 4;
    int p = blockIdx.x * 4 + w;  // pair 0..2047
    int b0 = 2 * p, b1 = b0 + 1;

    if (lane < 16) {
        sv[w][lane] = 0ull;       // v[-1] = 0 (overridden by first-iter h override anyway)
        sv[w][32 + lane] = 0ull;  // permanent zero zone for role0 reads
    }
    __syncwarp();

    // weights (pre-scaled); WA: role0=S*Whh0[i], role1=S*Whh1[i]. WB: role0=S*Wih1[i], role1=dummy.
    const float* wAp = (role ? Whh1 : Whh0) + i * 16;
    const float* wBp = (role ? Whh1 : Wih1) + i * 16;
    unsigned long long WA[16], WB[16];
#pragma unroll
    for (int j = 0; j < 16; j++) {
        float a = SCALE * wAp[j];
        float b = SCALE * wBp[j];
        WA[j] = pk2(a, a);
        WB[j] = pk2(b, b);
    }
    // dotB init: role0 carries the scaled layer-1 bias; role1 contributes junk (discarded)
    unsigned long long binit = 0ull;
    if (!role) {
        float bb = SCALE * (bih1[i] + bhh1[i]);
        binit = pk2(bb, bb);
    }
    // initial hidden state for this role's layer
    const float* hp = h0in + (size_t)role * BB * HH;
    unsigned long long sA[16];
#pragma unroll
    for (int j = 0; j < 16; j++) sA[j] = pk2(hp[b0 * 16 + j], hp[b1 * 16 + j]);
    // role1 first-iteration override value: its layer's init state for unit i
    unsigned long long h1ini = pk2(hp[b0 * 16 + i], hp[b1 * 16 + i]);

    // u stream: role0 streams real U; role1 points at the zero tail (stride 0)
    const unsigned long long* ubase =
        role ? (g_U + ZTAIL + i) : (g_U + (size_t)p * TT * 16 + i);
    const size_t ustride = role ? 0 : 16;
    const unsigned long long* uend = ubase + (size_t)(TT - 1) * ustride;
    unsigned long long ub0 = ubase[0];
    unsigned long long ub1 = ubase[ustride];
    const unsigned long long* upf = ubase + 2 * ustride;

    unsigned long long* myh = &sh[w][lane];
    unsigned long long* myv = &sv[w][role * 16 + i];
    const unsigned long long* vrd = &sv[w][role ? i : (32 + i)];
    const ulonglong2* hr = (const ulonglong2*)&sh[w][role * 16];

#define KB_STEP(UVAL, FIRST)                                                   \
    {                                                                          \
        unsigned long long a0 = fma2(WA[0], sA[0], 0ull);                      \
        unsigned long long a1 = fma2(WA[1], sA[1], 0ull);                      \
        a0 = fma2(WA[2], sA[2], a0);  a1 = fma2(WA[3], sA[3], a1);             \
        a0 = fma2(WA[4], sA[4], a0);  a1 = fma2(WA[5], sA[5], a1);             \
        a0 = fma2(WA[6], sA[6], a0);  a1 = fma2(WA[7], sA[7], a1);             \
        a0 = fma2(WA[8], sA[8], a0);  a1 = fma2(WA[9], sA[9], a1);             \
        a0 = fma2(WA[10], sA[10], a0); a1 = fma2(WA[11], sA[11], a1);          \
        a0 = fma2(WA[12], sA[12], a0); a1 = fma2(WA[13], sA[13], a1);          \
        a0 = fma2(WA[14], sA[14], a0); a1 = fma2(WA[15], sA[15], a1);          \
        unsigned long long vld = *vrd;                                         \
        unsigned long long z = add2(add2(add2(a0, a1), vld), (UVAL));          \
        unsigned long long h = tanh2_pre(z);                                   \
        if ((FIRST) && role) h = h1ini;                                        \
        *myh = h;                                                              \
        __syncwarp();                                                          \
        {                                                                      \
            ulonglong2 q0 = hr[0], q1 = hr[1], q2 = hr[2], q3 = hr[3];         \
            ulonglong2 q4 = hr[4], q5 = hr[5], q6 = hr[6], q7 = hr[7];         \
            sA[0] = q0.x; sA[1] = q0.y; sA[2] = q1.x; sA[3] = q1.y;            \
            sA[4] = q2.x; sA[5] = q2.y; sA[6] = q3.x; sA[7] = q3.y;            \
            sA[8] = q4.x; sA[9] = q4.y; sA[10] = q5.x; sA[11] = q5.y;          \
            sA[12] = q6.x; sA[13] = q6.y; sA[14] = q7.x; sA[15] = q7.y;        \
        }                                                                      \
        unsigned long long c0 = fma2(WB[0], sA[0], binit);                     \
        unsigned long long c1 = fma2(WB[1], sA[1], 0ull);                      \
        c0 = fma2(WB[2], sA[2], c0);  c1 = fma2(WB[3], sA[3], c1);             \
        c0 = fma2(WB[4], sA[4], c0);  c1 = fma2(WB[5], sA[5], c1);             \
        c0 = fma2(WB[6], sA[6], c0);  c1 = fma2(WB[7], sA[7], c1);             \
        c0 = fma2(WB[8], sA[8], c0);  c1 = fma2(WB[9], sA[9], c1);             \
        c0 = fma2(WB[10], sA[10], c0); c1 = fma2(WB[11], sA[11], c1);          \
        c0 = fma2(WB[12], sA[12], c0); c1 = fma2(WB[13], sA[13], c1);          \
        c0 = fma2(WB[14], sA[14], c0); c1 = fma2(WB[15], sA[15], c1);          \
        *myv = add2(c0, c1);                                                   \
        __syncwarp();                                                          \
    }

    // iteration m=0 (role1 output overridden to its init state)
    {
        unsigned long long uv = ub0;
        const unsigned long long* q = upf;  // u[2]
        ub0 = *q;
        upf += ustride;
        KB_STEP(uv, true);
    }
    // iterations m = 1..400 (401 total). role0 produces h0[m] (junk at m=400, unused);
    // role1 produces h1[m-1]; after the loop role1's sA = h1[399].
#pragma unroll 1
    for (int k = 0; k < 200; k++) {
        {
            unsigned long long uv = ub1;
            const unsigned long long* q = upf;
            if (q > uend) q = uend;
            ub1 = *q;
            upf += ustride;
            KB_STEP(uv, false);
        }
        {
            unsigned long long uv = ub0;
            const unsigned long long* q = upf;
            if (q > uend) q = uend;
            ub0 = *q;
            upf += ustride;
            KB_STEP(uv, false);
        }
    }
#undef KB_STEP

    // final FC (NC=2): role1 lanes hold full h1[399] in sA
    if (role && i < 2) {
        float bf = bfc[i];
        unsigned long long acc = pk2(bf, bf);
#pragma unroll
        for (int j = 0; j < 16; j++) {
            float wv = Wfc[i * 16 + j];
            acc = fma2(pk2(wv, wv), sA[j], acc);
        }
        float lo, hi;
        up2(acc, lo, hi);
        out[4 * p + i] = lo;
        out[4 * p + 2 + i] = hi;
    }
}

extern "C" void kernel_launch(void* const* d_in, const int* in_sizes, int n_in,
                              void* d_out, int out_size) {
    const float* x    = (const float*)d_in[0];
    const float* h0   = (const float*)d_in[1];
    const float* Wih0 = (const float*)d_in[2];
    const float* Whh0 = (const float*)d_in[3];
    const float* bih0 = (const float*)d_in[4];
    const float* bhh0 = (const float*)d_in[5];
    const float* Wih1 = (const float*)d_in[6];
    const float* Whh1 = (const float*)d_in[7];
    const float* bih1 = (const float*)d_in[8];
    const float* bhh1 = (const float*)d_in[9];
    const float* Wfc  = (const float*)d_in[10];
    const float* bfc  = (const float*)d_in[11];
    float* out = (float*)d_out;

    dim3 gA(25, 256);
    kA<<<gA, 128>>>(x, Wih0, bih0, bhh0);
    kB<<<512, 128>>>(h0, Whh0, Wih1, Whh1, bih1, bhh1, Wfc, bfc, out);
}